// round 1
// baseline (speedup 1.0000x reference)
#include <cuda_runtime.h>

// Problem constants
#define NN 512
#define KK 17
#define WW 48
#define HH 64
#define NK (NN * KK)              // 8704
#define HMSZ (HH * WW)            // 3072
#define TOTAL ((double)NN * KK * HH * WW)  // 26738688

__device__ double g_acc;

__global__ void zero_acc_kernel() {
    g_acc = 0.0;
}

__global__ __launch_bounds__(256) void reg2hm_loss_kernel(
    const float* __restrict__ pred,      // [N,K,2]
    const float* __restrict__ sigma,     // [N,K,2]
    const float* __restrict__ teacher,   // [N,K,H,W]
    const float* __restrict__ twgt)      // [N,K,1]
{
    const int nk  = blockIdx.x;          // 0..NK-1
    const int tid = threadIdx.x;

    __shared__ float ex[WW];
    __shared__ float ey[HH];
    __shared__ float s_params[5];        // mux, muy, sx, sy, coef
    __shared__ float s_warp[8];

    if (tid == 0) {
        float mux = pred[nk * 2 + 0] * (float)WW;
        float muy = pred[nk * 2 + 1] * (float)HH;
        float sx  = sigma[nk * 2 + 0];
        float sy  = sigma[nk * 2 + 1];
        float mask = ((mux - 3.0f * sx < (float)WW) &&
                      (muy - 3.0f * sy < (float)HH) &&
                      (mux + 3.0f * sx + 1.0f >= 0.0f) &&
                      (muy + 3.0f * sy + 1.0f >= 0.0f)) ? 1.0f : 0.0f;
        float tw = twgt[nk] * mask;
        s_params[0] = mux;
        s_params[1] = muy;
        s_params[2] = sx;
        s_params[3] = sy;
        s_params[4] = tw * tw;           // coef; zero whenever mask==0
    }
    __syncthreads();

    const float mux  = s_params[0];
    const float muy  = s_params[1];
    const float sx   = s_params[2];
    const float sy   = s_params[3];
    const float coef = s_params[4];
    const float invx = 1.0f / (sx * sx + 1e-9f);
    const float invy = 1.0f / (sy * sy + 1e-9f);

    if (tid < WW) {
        float d = (float)tid - mux;
        ex[tid] = __expf(-0.5f * d * d * invx);
    }
    if (tid >= 64 && tid < 64 + HH) {
        int h = tid - 64;
        float d = (float)h - muy;
        ey[h] = __expf(-0.5f * d * d * invy);
    }
    __syncthreads();

    // Stream teacher heatmap for this (n,k): 3072 floats = 768 float4.
    // Thread t handles float4 indices t, t+256, t+512. 12 float4 per row (W=48).
    const float4* tp = reinterpret_cast<const float4*>(teacher + (size_t)nk * HMSZ);
    float sum = 0.0f;
#pragma unroll
    for (int i = 0; i < 3; i++) {
        int q = tid + i * 256;           // 0..767
        float4 t4 = tp[q];
        int h = q / 12;                  // row (4 elems of a float4 share a row)
        int w = (q % 12) * 4;
        float eyh = ey[h];
        float d0 = ex[w + 0] * eyh - t4.x;
        float d1 = ex[w + 1] * eyh - t4.y;
        float d2 = ex[w + 2] * eyh - t4.z;
        float d3 = ex[w + 3] * eyh - t4.w;
        sum += d0 * d0 + d1 * d1 + d2 * d2 + d3 * d3;
    }
    sum *= coef;

    // Warp reduce
#pragma unroll
    for (int off = 16; off > 0; off >>= 1)
        sum += __shfl_down_sync(0xFFFFFFFFu, sum, off);
    if ((tid & 31) == 0) s_warp[tid >> 5] = sum;
    __syncthreads();
    if (tid < 8) {
        float v = s_warp[tid];
#pragma unroll
        for (int off = 4; off > 0; off >>= 1)
            v += __shfl_down_sync(0x000000FFu, v, off);
        if (tid == 0)
            atomicAdd(&g_acc, (double)v);
    }
}

__global__ void finalize_kernel(float* __restrict__ out) {
    out[0] = (float)(g_acc / TOTAL);     // LOSS_WEIGHT = 1.0
}

extern "C" void kernel_launch(void* const* d_in, const int* in_sizes, int n_in,
                              void* d_out, int out_size) {
    const float* pred    = (const float*)d_in[0];
    const float* sigma   = (const float*)d_in[1];
    const float* teacher = (const float*)d_in[2];
    const float* twgt    = (const float*)d_in[3];
    float* out = (float*)d_out;

    zero_acc_kernel<<<1, 1>>>();
    reg2hm_loss_kernel<<<NK, 256>>>(pred, sigma, teacher, twgt);
    finalize_kernel<<<1, 1>>>(out);
}